// round 1
// baseline (speedup 1.0000x reference)
#include <cuda_runtime.h>

// WaveNet autoregressive decode, restructured:
//   - 8-layer dilated causal conv stack (K=2, dilations 1..128) is LINEAR ->
//     compose into effective kernel E[256 taps][256 ch] + steady-state bias.
//   - Encoder contribution c_i[b][ch] precomputed for all 32 decode steps.
//   - Decode: feat_i = c_i + sum_{m<i} E[i-1-m] * o_m ; o_i = MLP(feat_i).
//     Batch-independent -> one CTA per batch runs all 32 steps in one launch.

#define DEC  32
#define NB   64
#define C    256
#define HID  512
#define TT   543
#define RF   256

__device__ float g_E[2][RF][C];       // [parity][tau][c] effective kernel
__device__ float g_bias[2][C];        // [parity][c]      effective bias
__device__ float g_wT[7][2][C][C];    // [layer][k][ci][co] transposed conv weights
__device__ float g_c[DEC][NB][C];     // encoder contributions per decode step

// ---------------------------------------------------------------------------
// prep: transpose conv weights for coalesced composition reads; init E from
// conv0 (Cin=1): E[0][c] = w[c,0,1] (lag 0), E[1][c] = w[c,0,0] (lag 1).
// ---------------------------------------------------------------------------
__global__ void prep_kernel(const float* __restrict__ c0w,
                            const float* __restrict__ c0b,
                            const float* __restrict__ cw) {
    int blk = blockIdx.x, t = threadIdx.x;
    if (blk < 7 * 256) {                      // weight transpose
        int j = blk >> 8, co = blk & 255, ci = t;
        float2 w = reinterpret_cast<const float2*>(cw)[(size_t)(j * C + co) * C + ci];
        g_wT[j][0][ci][co] = w.x;
        g_wT[j][1][ci][co] = w.y;
    } else {                                  // E / bias init
        int tau = blk - 7 * 256;              // 0..255
        float v = 0.f;
        if (tau == 0)      v = c0w[2 * t + 1];
        else if (tau == 1) v = c0w[2 * t];
        g_E[0][tau][t] = v;
        if (tau == 0) g_bias[0][t] = c0b[t];
    }
}

// ---------------------------------------------------------------------------
// comp: one layer of kernel composition.
//   Enew[tau][c] = sum_ci w[c,ci,1]*Eold[tau][ci] + w[c,ci,0]*Eold[tau-d][ci]
// Block handles 4 taus (grid 64) + one extra block for the bias recurrence:
//   bnew[c] = sum_ci (w0+w1)[ci][c]*bold[ci] + b_layer[c]
// Eold rows beyond the old receptive field are zero, so writing the full
// 256-tau range every layer keeps padding implicit.
// ---------------------------------------------------------------------------
__global__ void comp_kernel(int L, int d, int sp, const float* __restrict__ lb) {
    int dp = sp ^ 1;
    int t = threadIdx.x;
    if (blockIdx.x == 64) {                   // bias block
        float acc = lb[t];
        const float* w0 = &g_wT[L][0][0][t];
        const float* w1 = &g_wT[L][1][0][t];
        for (int ci = 0; ci < C; ci++)
            acc += (w0[ci * C] + w1[ci * C]) * g_bias[sp][ci];
        g_bias[dp][t] = acc;
        return;
    }
    __shared__ alignas(16) float A[4][C];
    __shared__ alignas(16) float Bs[4][C];
    int tau0 = blockIdx.x * 4;
    #pragma unroll
    for (int u = 0; u < 4; u++) {
        A[u][t] = g_E[sp][tau0 + u][t];
        int tm = tau0 + u - d;
        Bs[u][t] = (tm >= 0) ? g_E[sp][tm][t] : 0.f;
    }
    __syncthreads();
    float acc[4] = {0.f, 0.f, 0.f, 0.f};
    const float* w0p = &g_wT[L][0][0][t];
    const float* w1p = &g_wT[L][1][0][t];
    for (int q = 0; q < C / 4; q++) {
        float w1v[4], w0v[4];
        #pragma unroll
        for (int u = 0; u < 4; u++) {
            w1v[u] = w1p[(4 * q + u) * C];
            w0v[u] = w0p[(4 * q + u) * C];
        }
        #pragma unroll
        for (int u = 0; u < 4; u++) {
            float4 a  = reinterpret_cast<float4*>(A[u])[q];
            float4 bb = reinterpret_cast<float4*>(Bs[u])[q];
            acc[u] += a.x * w1v[0] + a.y * w1v[1] + a.z * w1v[2] + a.w * w1v[3]
                    + bb.x * w0v[0] + bb.y * w0v[1] + bb.z * w0v[2] + bb.w * w0v[3];
        }
    }
    #pragma unroll
    for (int u = 0; u < 4; u++)
        g_E[dp][tau0 + u][t] = acc[u];
}

// ---------------------------------------------------------------------------
// c: encoder contributions.
//   c[i][b][c] = b_eff[c] + sum_{tau=i..255} E[tau][c] * x[b][511+i-tau]
// Grid: 128 blocks = (batch, channel-half); 128 threads; acc[32] in regs.
// Only x[256..511] is ever touched (tau >= i excludes feedback slots).
// ---------------------------------------------------------------------------
__global__ void c_kernel(const float* __restrict__ x) {
    int b = blockIdx.x >> 1, half = blockIdx.x & 1;
    int t = threadIdx.x;
    int c = half * 128 + t;
    __shared__ float xs[256];                 // xs[k] = x[b][256+k]
    const float* xb = x + b * TT;
    for (int k = t; k < 256; k += 128) xs[k] = xb[256 + k];
    __syncthreads();
    float acc[DEC];
    float bv = g_bias[1][c];
    #pragma unroll
    for (int i = 0; i < DEC; i++) acc[i] = bv;
    for (int tau = 0; tau < 32; tau++) {      // triangular region (tau >= i)
        float e = g_E[1][tau][c];
        for (int i = 0; i <= tau; i++)
            acc[i] += e * xs[255 + i - tau];
    }
    for (int tau = 32; tau < RF; tau++) {     // full 32-wide region
        float e = g_E[1][tau][c];
        const float* xp = &xs[255 - tau];
        #pragma unroll
        for (int i = 0; i < DEC; i++)
            acc[i] += e * xp[i];
    }
    #pragma unroll
    for (int i = 0; i < DEC; i++) g_c[i][b][c] = acc[i];
}

// ---------------------------------------------------------------------------
// decode: one CTA per batch, all 32 autoregressive steps in-kernel.
// Thread t owns hidden units t and t+256. Per step:
//   h = ReLU(feat @ W1 + b1); o = h . w2 + b2; rank-1 update of future feats.
// All state is batch-local -> only __syncthreads() needed.
// ---------------------------------------------------------------------------
__global__ void __launch_bounds__(256) decode_kernel(
    const float* __restrict__ w1, const float* __restrict__ b1,
    const float* __restrict__ w2, const float* __restrict__ b2,
    float* __restrict__ out) {
    int b = blockIdx.x, t = threadIdx.x;
    __shared__ float cb[DEC][C];              // running feats (32 KB)
    __shared__ float w2s[HID];
    __shared__ float red[8];
    __shared__ float osh;
    #pragma unroll
    for (int i = 0; i < DEC; i++) cb[i][t] = g_c[i][b][t];
    w2s[t]       = w2[t];
    w2s[t + 256] = w2[t + 256];
    float b1a = b1[t], b1b = b1[t + 256];
    float b2v = b2[0];
    __syncthreads();

    for (int i = 0; i < DEC; i++) {
        float acc1 = b1a, acc2 = b1b;
        const float* wp = w1 + t;             // W1 row-major [C][HID]
        #pragma unroll 8
        for (int c = 0; c < C; c++) {
            float f = cb[i][c];
            acc1 += f * wp[(size_t)c * HID];
            acc2 += f * wp[(size_t)c * HID + 256];
        }
        acc1 = fmaxf(acc1, 0.f);
        acc2 = fmaxf(acc2, 0.f);
        float contrib = acc1 * w2s[t] + acc2 * w2s[t + 256];
        #pragma unroll
        for (int off = 16; off > 0; off >>= 1)
            contrib += __shfl_down_sync(0xffffffffu, contrib, off);
        if ((t & 31) == 0) red[t >> 5] = contrib;
        __syncthreads();
        if (t == 0) {
            float o = b2v;
            #pragma unroll
            for (int w = 0; w < 8; w++) o += red[w];
            osh = o;
            out[b * DEC + i] = o;
        }
        __syncthreads();
        float o = osh;
        for (int ip = i + 1; ip < DEC; ip++)  // feed o into future feats
            cb[ip][t] += g_E[1][ip - 1 - i][t] * o;
        __syncthreads();
    }
}

// ---------------------------------------------------------------------------
extern "C" void kernel_launch(void* const* d_in, const int* in_sizes, int n_in,
                              void* d_out, int out_size) {
    const float* inputs = (const float*)d_in[0];
    const float* c0w    = (const float*)d_in[1];
    const float* c0b    = (const float*)d_in[2];
    const float* cw     = (const float*)d_in[3];
    const float* cb     = (const float*)d_in[4];
    const float* w1     = (const float*)d_in[5];
    const float* b1     = (const float*)d_in[6];
    const float* w2     = (const float*)d_in[7];
    const float* b2     = (const float*)d_in[8];
    // d_in[9] = teacher_forcing_ratio (always 0 in this problem) -- unused.

    prep_kernel<<<7 * 256 + 256, 256>>>(c0w, c0b, cw);
    int sp = 0;
    for (int L = 0; L < 7; L++) {             // layers 2..8, dilation 2<<L
        comp_kernel<<<65, 256>>>(L, 2 << L, sp, cb + L * C);
        sp ^= 1;
    }
    // final E / bias live in parity 1 (7 flips from parity 0)
    c_kernel<<<128, 128>>>(inputs);
    decode_kernel<<<64, 256>>>(w1, b1, w2, b2, (float*)d_out);
}

// round 8
// speedup vs baseline: 3.4668x; 3.4668x over previous
#include <cuda_runtime.h>
#include <cstdint>

// WaveNet autoregressive decode, fully linearized:
//   - 8-layer dilated conv stack is affine -> effective kernel E[256][256] + bias
//   - encoder contributions c_i[b][ch] precomputed for all 32 steps
//   - HIDDEN-SPACE recursion: z_i = Z0_i + sum_m o_m * G[i-1-m], with
//     Z0 = c@W1 + b1 (one bulk GEMM) and G[r] = E[r]@W1 (tiny GEMM).
//     Decode loop touches W1 not at all; per-CTA, register-resident, 1 bar/step.

#define DEC  32
#define NB   64
#define C    256
#define HID  512
#define TT   543
#define RF   256

__device__ float g_E[2][RF][C];        // [parity][tau][c] effective kernel
__device__ float g_bias[2][C];         // [parity][c]      effective bias
__device__ float g_wT[7][2][C][C];     // [layer][k][ci][co] transposed conv weights
__device__ float g_c[DEC][NB][C];      // encoder contributions (feat space)
__device__ float g_G[DEC - 1][HID];    // G[r] = E[r] @ W1
__device__ float g_z[DEC][NB][HID];    // Z0 = c @ W1 + b1

// ---------------------------------------------------------------------------
// prep: transpose conv weights; init E from conv0 (Cin=1).
//   E[0][c] = w[c,0,1] (lag 0), E[1][c] = w[c,0,0] (lag 1), rest zero.
// ---------------------------------------------------------------------------
__global__ void prep_kernel(const float* __restrict__ c0w,
                            const float* __restrict__ c0b,
                            const float* __restrict__ cw) {
    int blk = blockIdx.x, t = threadIdx.x;
    if (blk < 7 * 256) {
        int j = blk >> 8, co = blk & 255, ci = t;
        float2 w = reinterpret_cast<const float2*>(cw)[(size_t)(j * C + co) * C + ci];
        g_wT[j][0][ci][co] = w.x;
        g_wT[j][1][ci][co] = w.y;
    } else {
        int tau = blk - 7 * 256;
        float v = 0.f;
        if (tau == 0)      v = c0w[2 * t + 1];
        else if (tau == 1) v = c0w[2 * t];
        g_E[0][tau][t] = v;
        if (tau == 0) g_bias[0][t] = c0b[t];
    }
}

// ---------------------------------------------------------------------------
// comp: one layer of kernel composition (latency-optimized).
//   Enew[tau][co] = sum_ci w1[ci][co]*Eold[tau][ci] + w0[ci][co]*Eold[tau-d][ci]
// Layer L outputs NT = 4<<L live taps; rows NT..min(2NT,256)-1 are zeroed so
// the next layer's reads stay defined. Block = 4 taus x 128 co, ci split
// 4-way across 512 threads, partials combined through smem.
// ---------------------------------------------------------------------------
__global__ void __launch_bounds__(512) comp_kernel(
    int L, int d, int NT, int sp, const float* __restrict__ lb) {
    int dp = sp ^ 1;
    int nblk = (int)gridDim.x - 1;
    if ((int)blockIdx.x == nblk) {            // bias recurrence block
        __shared__ float br[2][256];
        int t = threadIdx.x & 255, s2 = threadIdx.x >> 8;
        const float* w0 = &g_wT[L][0][0][t];
        const float* w1p = &g_wT[L][1][0][t];
        float acc = 0.f;
        for (int ci = 128 * s2; ci < 128 * s2 + 128; ci++)
            acc += (w0[ci * C] + w1p[ci * C]) * g_bias[sp][ci];
        br[s2][t] = acc;
        __syncthreads();
        if (s2 == 0) g_bias[dp][t] = lb[t] + br[0][t] + br[1][t];
        return;
    }
    int tl = threadIdx.x & 127;
    int s  = threadIdx.x >> 7;                // 0..3  ci-quarter
    int tau0 = (int)(blockIdx.x >> 1) * 4;
    int co  = ((blockIdx.x & 1) << 7) + tl;
    if (tau0 >= NT) {                          // zero-pad rows NT..2NT-1
        g_E[dp][tau0 + s][co] = 0.f;
        return;
    }
    __shared__ alignas(16) float A[4][C], B[4][C];
    __shared__ float red[4][4][128];
    for (int r = threadIdx.x; r < 1024; r += 512) {
        int u = r >> 8, c = r & 255;
        A[u][c] = g_E[sp][tau0 + u][c];
        int tm = tau0 + u - d;
        B[u][c] = (tm >= 0) ? g_E[sp][tm][c] : 0.f;
    }
    __syncthreads();
    float acc[4] = {0.f, 0.f, 0.f, 0.f};
    const float* w0p = &g_wT[L][0][0][co];
    const float* w1p = &g_wT[L][1][0][co];
    int ci0 = s * 64;
    #pragma unroll 4
    for (int q = 0; q < 16; q++) {
        int ci = ci0 + 4 * q;
        float w1v[4], w0v[4];
        #pragma unroll
        for (int j = 0; j < 4; j++) {
            w1v[j] = w1p[(size_t)(ci + j) * C];
            w0v[j] = w0p[(size_t)(ci + j) * C];
        }
        #pragma unroll
        for (int u = 0; u < 4; u++) {
            float4 a  = *(const float4*)&A[u][ci];
            float4 bb = *(const float4*)&B[u][ci];
            acc[u] += a.x * w1v[0] + a.y * w1v[1] + a.z * w1v[2] + a.w * w1v[3]
                    + bb.x * w0v[0] + bb.y * w0v[1] + bb.z * w0v[2] + bb.w * w0v[3];
        }
    }
    #pragma unroll
    for (int u = 0; u < 4; u++) red[s][u][tl] = acc[u];
    __syncthreads();
    if (s == 0) {
        #pragma unroll
        for (int u = 0; u < 4; u++)
            g_E[dp][tau0 + u][co] =
                red[0][u][tl] + red[1][u][tl] + red[2][u][tl] + red[3][u][tl];
    }
}

// ---------------------------------------------------------------------------
// c: encoder contributions (feat space).
//   c[i][b][c] = b_eff[c] + sum_{tau=i..255} E[tau][c] * x[b][511+i-tau]
// ---------------------------------------------------------------------------
__global__ void c_kernel(const float* __restrict__ x) {
    int b = blockIdx.x >> 1, half = blockIdx.x & 1;
    int t = threadIdx.x;
    int c = half * 128 + t;
    __shared__ float xs[256];
    const float* xb = x + b * TT;
    for (int k = t; k < 256; k += 128) xs[k] = xb[256 + k];
    __syncthreads();
    float acc[DEC];
    float bv = g_bias[1][c];
    #pragma unroll
    for (int i = 0; i < DEC; i++) acc[i] = bv;
    for (int tau = 0; tau < 32; tau++) {
        float e = g_E[1][tau][c];
        for (int i = 0; i <= tau; i++)
            acc[i] += e * xs[255 + i - tau];
    }
    for (int tau = 32; tau < RF; tau++) {
        float e = g_E[1][tau][c];
        const float* xp = &xs[255 - tau];
        #pragma unroll
        for (int i = 0; i < DEC; i++)
            acc[i] += e * xp[i];
    }
    #pragma unroll
    for (int i = 0; i < DEC; i++) g_c[i][b][c] = acc[i];
}

// ---------------------------------------------------------------------------
// g: G[r][h] = sum_c E[1][r][c] * W1[c][h], r in 0..30.
// grid 124 = 31 r x 4 h-quarters; block 128.
// ---------------------------------------------------------------------------
__global__ void g_kernel(const float* __restrict__ w1) {
    int r = blockIdx.x >> 2, hq = blockIdx.x & 3;
    int h = hq * 128 + threadIdx.x;
    float acc = 0.f;
    const float* ep = &g_E[1][r][0];
    #pragma unroll 8
    for (int c = 0; c < C; c++)
        acc += ep[c] * w1[(size_t)c * HID + h];
    g_G[r][h] = acc;
}

// ---------------------------------------------------------------------------
// z0: bulk GEMM  Z0[row][h] = g_c_flat[row][:] @ W1[:, h] + b1[h]
// rows = (i,b) flattened: 2048 x 256 @ 256 x 512.
// grid (32, 4): 64-row x 128-col tiles; block 256; thread tile 8M x 4N.
// ---------------------------------------------------------------------------
__global__ void __launch_bounds__(256) z0_kernel(
    const float* __restrict__ w1, const float* __restrict__ b1) {
    __shared__ alignas(16) float As[32][68];   // [k][m], padded (68%32=4)
    __shared__ alignas(16) float Bs[32][128];  // [k][n]
    int t  = threadIdx.x;
    int tx = t & 31;            // n-group: cols tx*4 .. tx*4+3
    int ty = t >> 5;            // m-group: rows ty*8 .. ty*8+7
    int row0 = blockIdx.x * 64;
    int col0 = blockIdx.y * 128;
    const float* gc = &g_c[0][0][0];           // flat [2048][256]
    float acc[8][4];
    #pragma unroll
    for (int m = 0; m < 8; m++)
        #pragma unroll
        for (int n = 0; n < 4; n++) acc[m][n] = 0.f;

    for (int kk = 0; kk < 256; kk += 32) {
        #pragma unroll
        for (int u = 0; u < 8; u++) {          // A: 64m x 32k
            int idx = u * 256 + t;
            int m = idx >> 5, k = idx & 31;
            As[k][m] = gc[(size_t)(row0 + m) * C + kk + k];
        }
        #pragma unroll
        for (int u = 0; u < 16; u++) {         // B: 32k x 128n
            int idx = u * 256 + t;
            int k = idx >> 7, n = idx & 127;
            Bs[k][n] = w1[(size_t)(kk + k) * HID + col0 + n];
        }
        __syncthreads();
        #pragma unroll
        for (int k = 0; k < 32; k++) {
            float4 bv = *(const float4*)&Bs[k][tx * 4];
            float4 a0 = *(const float4*)&As[k][ty * 8];
            float4 a1 = *(const float4*)&As[k][ty * 8 + 4];
            float am[8] = {a0.x, a0.y, a0.z, a0.w, a1.x, a1.y, a1.z, a1.w};
            float bn[4] = {bv.x, bv.y, bv.z, bv.w};
            #pragma unroll
            for (int m = 0; m < 8; m++)
                #pragma unroll
                for (int n = 0; n < 4; n++)
                    acc[m][n] += am[m] * bn[n];
        }
        __syncthreads();
    }
    float* gz = &g_z[0][0][0];                 // flat [2048][512]
    float b1v[4];
    #pragma unroll
    for (int n = 0; n < 4; n++) b1v[n] = b1[col0 + tx * 4 + n];
    #pragma unroll
    for (int m = 0; m < 8; m++) {
        float4 o = make_float4(acc[m][0] + b1v[0], acc[m][1] + b1v[1],
                               acc[m][2] + b1v[2], acc[m][3] + b1v[3]);
        *(float4*)&gz[(size_t)(row0 + ty * 8 + m) * HID + col0 + tx * 4] = o;
    }
}

// ---------------------------------------------------------------------------
// decode: one CTA per batch, 512 threads, thread t owns hidden unit t.
// z[32] and G[31] live in REGISTERS; per step: relu dot w2, block-reduce
// (shfl + double-buffered warp partials -> single __syncthreads), every
// thread redundantly sums the 16 partials (no second barrier), then <=31
// register FFMAs feed o into future z's. No cross-CTA sync anywhere.
// ---------------------------------------------------------------------------
__global__ void __launch_bounds__(512) decode_kernel(
    const float* __restrict__ w2, const float* __restrict__ b2,
    float* __restrict__ out) {
    int b = blockIdx.x, t = threadIdx.x;
    __shared__ float wpart[2][16];
    float z[DEC], G[DEC - 1];
    #pragma unroll
    for (int i = 0; i < DEC; i++) z[i] = g_z[i][b][t];
    #pragma unroll
    for (int r = 0; r < DEC - 1; r++) G[r] = g_G[r][t];
    float w2v = w2[t], b2v = b2[0];
    int warp = t >> 5, lane = t & 31;

    #pragma unroll
    for (int i = 0; i < DEC; i++) {
        float p = fmaxf(z[i], 0.f) * w2v;
        #pragma unroll
        for (int off = 16; off > 0; off >>= 1)
            p += __shfl_down_sync(0xffffffffu, p, off);
        if (lane == 0) wpart[i & 1][warp] = p;
        __syncthreads();
        float o = b2v;
        #pragma unroll
        for (int w = 0; w < 16; w++) o += wpart[i & 1][w];
        if (t == 0) out[b * DEC + i] = o;
        #pragma unroll
        for (int ip = i + 1; ip < DEC; ip++)
            z[ip] += o * G[ip - 1 - i];
    }
}

// ---------------------------------------------------------------------------
extern "C" void kernel_launch(void* const* d_in, const int* in_sizes, int n_in,
                              void* d_out, int out_size) {
    const float* inputs = (const float*)d_in[0];
    const float* c0w    = (const float*)d_in[1];
    const float* c0b    = (const float*)d_in[2];
    const float* cw     = (const float*)d_in[3];
    const float* cb     = (const float*)d_in[4];
    const float* w1     = (const float*)d_in[5];
    const float* b1     = (const float*)d_in[6];
    const float* w2     = (const float*)d_in[7];
    const float* b2     = (const float*)d_in[8];
    // d_in[9] = teacher_forcing_ratio (always 0) -- unused.

    prep_kernel<<<7 * 256 + 256, 256>>>(c0w, c0b, cw);
    int sp = 0;
    for (int L = 0; L < 7; L++) {
        int NT  = 4 << L;
        int NTz = (2 * NT < 256) ? 2 * NT : 256;
        int grid = (NTz / 4) * 2 + 1;
        comp_kernel<<<grid, 512>>>(L, 2 << L, NT, sp, cb + L * C);
        sp ^= 1;
    }
    // final E / bias in parity 1 (7 flips from parity 0)
    c_kernel<<<128, 128>>>(inputs);
    g_kernel<<<(DEC - 1) * 4, 128>>>(w1);
    dim3 zgrid(32, 4);
    z0_kernel<<<zgrid, 256>>>(w1, b1);
    decode_kernel<<<NB, 512>>>(w2, b2, (float*)d_out);
}